// round 3
// baseline (speedup 1.0000x reference)
#include <cuda_runtime.h>
#include <cstdint>

#define BQ 4
#define TT 4096
#define DD 1024
#define MM (BQ * TT)          // 16384 rows
#define NCH 64                // chunks along T
#define CHUNK 64              // T / NCH

#define BM 128
#define BN 128
#define BK 16
#define NSTAGE 3
#define KTILES (DD / BK)      // 64
#define APAD 20               // words per A row (conflict-free)
#define BPAD 136              // words per B row (conflict-free)

// ---- scratch (__device__ globals: allocation-free rule) ----
__device__ float g_xr[(size_t)MM * DD];     // tf32-rounded X
__device__ float g_wzr[(size_t)DD * DD];    // tf32-rounded Wz
__device__ float g_whr[(size_t)DD * DD];    // tf32-rounded Wh
__device__ float g_a[(size_t)MM * DD];      // a_t = 1 - z_t
__device__ float g_b[(size_t)MM * DD];      // b_t = z_t * htilde_t
__device__ float g_cA[BQ * NCH * DD];
__device__ float g_cB[BQ * NCH * DD];
__device__ float g_cH[BQ * NCH * DD];

__device__ __forceinline__ float tf32r(float x) {
    uint32_t r;
    asm("cvt.rna.tf32.f32 %0, %1;" : "=r"(r) : "f"(x));
    return __uint_as_float(r);
}

__device__ __forceinline__ void mma_tf32(float c[4], const uint32_t a[4], const uint32_t b[2]) {
    asm volatile(
        "mma.sync.aligned.m16n8k8.row.col.f32.tf32.tf32.f32 "
        "{%0,%1,%2,%3}, {%4,%5,%6,%7}, {%8,%9}, {%0,%1,%2,%3};\n"
        : "+f"(c[0]), "+f"(c[1]), "+f"(c[2]), "+f"(c[3])
        : "r"(a[0]), "r"(a[1]), "r"(a[2]), "r"(a[3]),
          "r"(b[0]), "r"(b[1]));
}

// ============================================================
// Elementwise tf32 rounding (so GEMM can cp.async raw bits).
// ============================================================
__global__ void round_tf32_kernel(const float4* __restrict__ src,
                                  float4* __restrict__ dst, int n4)
{
    int i = blockIdx.x * blockDim.x + threadIdx.x;
    if (i < n4) {
        float4 v = src[i];
        v.x = tf32r(v.x); v.y = tf32r(v.y); v.z = tf32r(v.z); v.w = tf32r(v.w);
        dst[i] = v;
    }
}

// ============================================================
// Fused dual GEMM: computes yz = X@Wz+bz and yh = X@Wh+bh for the
// same 128x128 tile, then stores a = 1-sigmoid(yz), b = sigmoid(yz)*yh.
// cp.async 3-stage pipeline, BK=16. 8 warps = 2(m) x 4(n), warp 64x32.
// ============================================================
__global__ __launch_bounds__(256)
void dual_gemm_kernel(const float* __restrict__ bz, const float* __restrict__ bh)
{
    extern __shared__ float smem[];
    float* As = smem;                          // [NSTAGE][BM][APAD]
    float* Bs = smem + NSTAGE * BM * APAD;     // [NSTAGE][2][BK][BPAD]

    const int tid  = threadIdx.x;
    const int warp = tid >> 5, lane = tid & 31;
    const int wm = warp >> 2, wn = warp & 3;
    const int g = lane >> 2, t = lane & 3;
    const int bm = blockIdx.y, bn = blockIdx.x;

    float accz[4][4][4], acch[4][4][4];
    #pragma unroll
    for (int i = 0; i < 4; i++)
        #pragma unroll
        for (int j = 0; j < 4; j++)
            #pragma unroll
            for (int k = 0; k < 4; k++) { accz[i][j][k] = 0.f; acch[i][j][k] = 0.f; }

    auto load_stage = [&](int kt, int s) {
        // A tile: 128 x 16 floats = 512 float4; 2 per thread
        #pragma unroll
        for (int i = 0; i < 2; i++) {
            int idx = tid * 2 + i;
            int row = idx >> 2, c4 = idx & 3;
            const float* srcp = &g_xr[(size_t)(bm * BM + row) * DD + kt * BK + c4 * 4];
            uint32_t d = (uint32_t)__cvta_generic_to_shared(
                &As[s * BM * APAD + row * APAD + c4 * 4]);
            asm volatile("cp.async.cg.shared.global [%0], [%1], 16;\n" :: "r"(d), "l"(srcp));
        }
        // B tiles (Wz, Wh): 2 x (16 x 128) = 1024 float4; 4 per thread
        #pragma unroll
        for (int i = 0; i < 4; i++) {
            int idx = tid * 4 + i;
            int w = idx >> 9, rem = idx & 511;
            int row = rem >> 5, c4 = rem & 31;
            const float* wp = w ? g_whr : g_wzr;
            const float* srcp = &wp[(size_t)(kt * BK + row) * DD + bn * BN + c4 * 4];
            uint32_t d = (uint32_t)__cvta_generic_to_shared(
                &Bs[((s * 2 + w) * BK + row) * BPAD + c4 * 4]);
            asm volatile("cp.async.cg.shared.global [%0], [%1], 16;\n" :: "r"(d), "l"(srcp));
        }
    };

    // prologue: stages 0..NSTAGE-2
    #pragma unroll
    for (int kt = 0; kt < NSTAGE - 1; kt++) {
        load_stage(kt, kt);
        asm volatile("cp.async.commit_group;\n");
    }

    int s = 0, sn = NSTAGE - 1;
    for (int kt = 0; kt < KTILES; kt++) {
        asm volatile("cp.async.wait_group 1;\n");
        __syncthreads();

        int ktn = kt + NSTAGE - 1;
        if (ktn < KTILES) load_stage(ktn, sn);
        asm volatile("cp.async.commit_group;\n");

        const float* Asw = &As[s * BM * APAD + wm * 64 * APAD];
        const float* Bs0 = &Bs[(s * 2 + 0) * BK * BPAD + wn * 32];
        const float* Bs1 = &Bs[(s * 2 + 1) * BK * BPAD + wn * 32];

        #pragma unroll
        for (int ks = 0; ks < 2; ks++) {
            const int kk = ks * 8 + t;
            uint32_t af[4][4], b0[4][2], b1[4][2];
            #pragma unroll
            for (int mf = 0; mf < 4; mf++) {
                const float* p = Asw + (mf * 16 + g) * APAD;
                af[mf][0] = __float_as_uint(p[kk]);
                af[mf][1] = __float_as_uint(p[8 * APAD + kk]);
                af[mf][2] = __float_as_uint(p[kk + 4]);
                af[mf][3] = __float_as_uint(p[8 * APAD + kk + 4]);
            }
            #pragma unroll
            for (int nf = 0; nf < 4; nf++) {
                int n = nf * 8 + g;
                b0[nf][0] = __float_as_uint(Bs0[kk * BPAD + n]);
                b0[nf][1] = __float_as_uint(Bs0[(kk + 4) * BPAD + n]);
                b1[nf][0] = __float_as_uint(Bs1[kk * BPAD + n]);
                b1[nf][1] = __float_as_uint(Bs1[(kk + 4) * BPAD + n]);
            }
            #pragma unroll
            for (int mf = 0; mf < 4; mf++)
                #pragma unroll
                for (int nf = 0; nf < 4; nf++) {
                    mma_tf32(accz[mf][nf], af[mf], b0[nf]);
                    mma_tf32(acch[mf][nf], af[mf], b1[nf]);
                }
        }
        s  = (s  + 1 == NSTAGE) ? 0 : s  + 1;
        sn = (sn + 1 == NSTAGE) ? 0 : sn + 1;
    }

    // epilogue: a = 1 - sigmoid(yz), b = sigmoid(yz) * yh
    #pragma unroll
    for (int nf = 0; nf < 4; nf++) {
        int col = bn * BN + wn * 32 + nf * 8 + 2 * t;
        float bz0 = bz[col], bz1 = bz[col + 1];
        float bh0 = bh[col], bh1 = bh[col + 1];
        #pragma unroll
        for (int mf = 0; mf < 4; mf++) {
            int row0 = bm * BM + wm * 64 + mf * 16 + g;
            float z0 = 1.f / (1.f + __expf(-(accz[mf][nf][0] + bz0)));
            float z1 = 1.f / (1.f + __expf(-(accz[mf][nf][1] + bz1)));
            float z2 = 1.f / (1.f + __expf(-(accz[mf][nf][2] + bz0)));
            float z3 = 1.f / (1.f + __expf(-(accz[mf][nf][3] + bz1)));
            float2 a01 = make_float2(1.f - z0, 1.f - z1);
            float2 a23 = make_float2(1.f - z2, 1.f - z3);
            float2 b01 = make_float2(z0 * (acch[mf][nf][0] + bh0),
                                     z1 * (acch[mf][nf][1] + bh1));
            float2 b23 = make_float2(z2 * (acch[mf][nf][2] + bh0),
                                     z3 * (acch[mf][nf][3] + bh1));
            *(float2*)&g_a[(size_t)row0 * DD + col] = a01;
            *(float2*)&g_b[(size_t)row0 * DD + col] = b01;
            *(float2*)&g_a[(size_t)(row0 + 8) * DD + col] = a23;
            *(float2*)&g_b[(size_t)(row0 + 8) * DD + col] = b23;
        }
    }
}

// ============================================================
// Scan phase 1: per-chunk composition (float4, 4 channels/thread).
// grid (NCH, BQ), 256 threads.
// ============================================================
__global__ void scan_reduce_kernel()
{
    const int tid = threadIdx.x;
    const int c = blockIdx.x, b = blockIdx.y;
    const float4* A4 = (const float4*)g_a;
    const float4* B4 = (const float4*)g_b;
    size_t base = ((size_t)(b * TT + c * CHUNK)) * (DD / 4) + tid;
    float4 A = make_float4(1.f, 1.f, 1.f, 1.f);
    float4 Bc = make_float4(0.f, 0.f, 0.f, 0.f);
    #pragma unroll 8
    for (int i = 0; i < CHUNK; i++) {
        float4 a = A4[base], v = B4[base];
        Bc.x = fmaf(a.x, Bc.x, v.x); A.x *= a.x;
        Bc.y = fmaf(a.y, Bc.y, v.y); A.y *= a.y;
        Bc.z = fmaf(a.z, Bc.z, v.z); A.z *= a.z;
        Bc.w = fmaf(a.w, Bc.w, v.w); A.w *= a.w;
        base += DD / 4;
    }
    int idx = (b * NCH + c) * (DD / 4) + tid;
    ((float4*)g_cA)[idx] = A;
    ((float4*)g_cB)[idx] = Bc;
}

// ============================================================
// Scan phase 2: serial scan over chunk carries. grid (BQ), 256 thr.
// ============================================================
__global__ void scan_carry_kernel()
{
    const int tid = threadIdx.x;
    const int b = blockIdx.x;
    float4 h = make_float4(0.f, 0.f, 0.f, 0.f);
    #pragma unroll
    for (int c = 0; c < NCH; c++) {
        int idx = (b * NCH + c) * (DD / 4) + tid;
        ((float4*)g_cH)[idx] = h;
        float4 A = ((const float4*)g_cA)[idx];
        float4 Bc = ((const float4*)g_cB)[idx];
        h.x = fmaf(A.x, h.x, Bc.x);
        h.y = fmaf(A.y, h.y, Bc.y);
        h.z = fmaf(A.z, h.z, Bc.z);
        h.w = fmaf(A.w, h.w, Bc.w);
    }
}

// ============================================================
// Scan phase 3: rescan each chunk from carry, write output.
// ============================================================
__global__ void scan_apply_kernel(float4* __restrict__ out)
{
    const int tid = threadIdx.x;
    const int c = blockIdx.x, b = blockIdx.y;
    const float4* A4 = (const float4*)g_a;
    const float4* B4 = (const float4*)g_b;
    size_t base = ((size_t)(b * TT + c * CHUNK)) * (DD / 4) + tid;
    float4 h = ((const float4*)g_cH)[(b * NCH + c) * (DD / 4) + tid];
    #pragma unroll 8
    for (int i = 0; i < CHUNK; i++) {
        float4 a = A4[base], v = B4[base];
        h.x = fmaf(a.x, h.x, v.x);
        h.y = fmaf(a.y, h.y, v.y);
        h.z = fmaf(a.z, h.z, v.z);
        h.w = fmaf(a.w, h.w, v.w);
        out[base] = h;
        base += DD / 4;
    }
}

// ============================================================
extern "C" void kernel_launch(void* const* d_in, const int* in_sizes, int n_in,
                              void* d_out, int out_size)
{
    const float* x  = (const float*)d_in[0];
    const float* Wz = (const float*)d_in[1];
    const float* bz = (const float*)d_in[2];
    const float* Wh = (const float*)d_in[3];
    const float* bh = (const float*)d_in[4];
    float4* out = (float4*)d_out;

    // Unconditional every call (no static guards — harness rule). Idempotent,
    // non-stream runtime call; legal under graph capture.
    const int smem_bytes = (NSTAGE * BM * APAD + NSTAGE * 2 * BK * BPAD) * 4;
    cudaFuncSetAttribute(dual_gemm_kernel,
                         cudaFuncAttributeMaxDynamicSharedMemorySize, smem_bytes);

    float* xr;  cudaGetSymbolAddress((void**)&xr,  g_xr);
    float* wzr; cudaGetSymbolAddress((void**)&wzr, g_wzr);
    float* whr; cudaGetSymbolAddress((void**)&whr, g_whr);

    // tf32 pre-rounding
    int n4x = MM * DD / 4;
    int n4w = DD * DD / 4;
    round_tf32_kernel<<<(n4x + 255) / 256, 256>>>((const float4*)x,  (float4*)xr,  n4x);
    round_tf32_kernel<<<(n4w + 255) / 256, 256>>>((const float4*)Wz, (float4*)wzr, n4w);
    round_tf32_kernel<<<(n4w + 255) / 256, 256>>>((const float4*)Wh, (float4*)whr, n4w);

    // fused dual GEMM -> (a, b)
    dual_gemm_kernel<<<dim3(DD / BN, MM / BM), 256, smem_bytes>>>(bz, bh);

    // chunked associative scan
    scan_reduce_kernel<<<dim3(NCH, BQ), 256>>>();
    scan_carry_kernel<<<BQ, 256>>>();
    scan_apply_kernel<<<dim3(NCH, BQ), 256>>>(out);
}

// round 5
// speedup vs baseline: 1.1305x; 1.1305x over previous
#include <cuda_runtime.h>
#include <cstdint>

#define BQ 4
#define TT 4096
#define DD 1024
#define MM (BQ * TT)          // 16384 rows
#define NCH 64                // chunks along T
#define CHUNK 64              // T / NCH

#define BM 128
#define BN 64
#define BK 16
#define NSTAGE 4
#define KTILES (DD / BK)      // 64
#define APAD 20               // words per A row (conflict-free)
#define BPAD 72               // words per B row (conflict-free)
#define A_STG (BM * APAD)               // 2560 words
#define B_STG (2 * BK * BPAD)           // 2304 words
#define STG_WORDS (A_STG + B_STG)       // 4864 words / stage

// ---- scratch (__device__ globals: allocation-free rule) ----
__device__ float g_xr[(size_t)MM * DD];     // tf32-rounded X
__device__ float g_wzr[(size_t)DD * DD];    // tf32-rounded Wz
__device__ float g_whr[(size_t)DD * DD];    // tf32-rounded Wh
__device__ float g_a[(size_t)MM * DD];      // a_t = 1 - z_t
__device__ float g_b[(size_t)MM * DD];      // b_t = z_t * htilde_t
__device__ float g_cA[BQ * NCH * DD];
__device__ float g_cB[BQ * NCH * DD];
__device__ float g_cH[BQ * NCH * DD];

__device__ __forceinline__ float tf32r(float x) {
    uint32_t r;
    asm("cvt.rna.tf32.f32 %0, %1;" : "=r"(r) : "f"(x));
    return __uint_as_float(r);
}

__device__ __forceinline__ void mma_tf32(float c[4], const uint32_t a[4], const uint32_t b[2]) {
    asm volatile(
        "mma.sync.aligned.m16n8k8.row.col.f32.tf32.tf32.f32 "
        "{%0,%1,%2,%3}, {%4,%5,%6,%7}, {%8,%9}, {%0,%1,%2,%3};\n"
        : "+f"(c[0]), "+f"(c[1]), "+f"(c[2]), "+f"(c[3])
        : "r"(a[0]), "r"(a[1]), "r"(a[2]), "r"(a[3]),
          "r"(b[0]), "r"(b[1]));
}

// ============================================================
// Elementwise tf32 rounding (so GEMM can cp.async raw bits).
// ============================================================
__global__ void round_tf32_kernel(const float4* __restrict__ src,
                                  float4* __restrict__ dst, int n4)
{
    int i = blockIdx.x * blockDim.x + threadIdx.x;
    if (i < n4) {
        float4 v = src[i];
        v.x = tf32r(v.x); v.y = tf32r(v.y); v.z = tf32r(v.z); v.w = tf32r(v.w);
        dst[i] = v;
    }
}

// ============================================================
// Fused dual GEMM, occupancy-tuned: block 128x64, 8 warps = 4(m) x 2(n),
// warp tile 32x32 PER OUTPUT (accz+acch = 64 regs). 4-stage cp.async.
// Epilogue stores a = 1-sigmoid(yz), b = sigmoid(yz)*(yh).
// ============================================================
__global__ __launch_bounds__(256, 2)
void dual_gemm_kernel(const float* __restrict__ bz, const float* __restrict__ bh)
{
    extern __shared__ float smem[];   // [NSTAGE][STG_WORDS]: A then B(z), B(h)

    const int tid  = threadIdx.x;
    const int warp = tid >> 5, lane = tid & 31;
    const int wm = warp >> 1, wn = warp & 1;    // 4 x 2 warp grid
    const int g = lane >> 2, t = lane & 3;
    const int bm = blockIdx.y, bn = blockIdx.x;

    float accz[2][4][4], acch[2][4][4];
    #pragma unroll
    for (int i = 0; i < 2; i++)
        #pragma unroll
        for (int j = 0; j < 4; j++)
            #pragma unroll
            for (int k = 0; k < 4; k++) { accz[i][j][k] = 0.f; acch[i][j][k] = 0.f; }

    // per-thread load coords (invariant across stages)
    const int a_row = tid >> 1, a_c4 = (tid & 1) * 2;          // 2 float4/thread
    const int b_w   = tid >> 7;                                 // 0: Wz, 1: Wh
    const int b_rem = tid & 127;
    const int b_row = b_rem >> 3, b_c4 = b_rem & 7;

    auto load_stage = [&](int kt, int s) {
        float* stg = smem + s * STG_WORDS;
        // A tile: 128 x 16 = 512 float4; 2 contiguous float4 per thread
        {
            const float* srcp = &g_xr[(size_t)(bm * BM + a_row) * DD + kt * BK + a_c4 * 4];
            uint32_t d = (uint32_t)__cvta_generic_to_shared(&stg[a_row * APAD + a_c4 * 4]);
            asm volatile("cp.async.cg.shared.global [%0], [%1], 16;\n" :: "r"(d), "l"(srcp));
            asm volatile("cp.async.cg.shared.global [%0], [%1], 16;\n"
                         :: "r"(d + 16), "l"(srcp + 4));
        }
        // B tiles (Wz, Wh): 2 x (16 rows x 16 float4); 2 float4 per thread
        {
            const float* wp = b_w ? g_whr : g_wzr;
            #pragma unroll
            for (int i = 0; i < 2; i++) {
                int c4 = b_c4 * 2 + i;          // 0..15 (64 cols)
                const float* srcp = &wp[(size_t)(kt * BK + b_row) * DD + bn * BN + c4 * 4];
                uint32_t d = (uint32_t)__cvta_generic_to_shared(
                    &stg[A_STG + (b_w * BK + b_row) * BPAD + c4 * 4]);
                asm volatile("cp.async.cg.shared.global [%0], [%1], 16;\n" :: "r"(d), "l"(srcp));
            }
        }
    };

    // prologue: stages 0..NSTAGE-2
    #pragma unroll
    for (int kt = 0; kt < NSTAGE - 1; kt++) {
        load_stage(kt, kt);
        asm volatile("cp.async.commit_group;\n");
    }

    int s = 0, sn = NSTAGE - 1;
    for (int kt = 0; kt < KTILES; kt++) {
        asm volatile("cp.async.wait_group %0;\n" :: "n"(NSTAGE - 2));
        __syncthreads();

        int ktn = kt + NSTAGE - 1;
        if (ktn < KTILES) load_stage(ktn, sn);
        asm volatile("cp.async.commit_group;\n");

        const float* Asw = smem + s * STG_WORDS + (wm * 32) * APAD;
        const float* Bs0 = smem + s * STG_WORDS + A_STG + wn * 32;
        const float* Bs1 = Bs0 + BK * BPAD;

        #pragma unroll
        for (int ks = 0; ks < 2; ks++) {
            const int kk = ks * 8 + t;
            uint32_t af[2][4], b0[4][2], b1[4][2];
            #pragma unroll
            for (int mf = 0; mf < 2; mf++) {
                const float* p = Asw + (mf * 16 + g) * APAD;
                af[mf][0] = __float_as_uint(p[kk]);
                af[mf][1] = __float_as_uint(p[8 * APAD + kk]);
                af[mf][2] = __float_as_uint(p[kk + 4]);
                af[mf][3] = __float_as_uint(p[8 * APAD + kk + 4]);
            }
            #pragma unroll
            for (int nf = 0; nf < 4; nf++) {
                int n = nf * 8 + g;
                b0[nf][0] = __float_as_uint(Bs0[kk * BPAD + n]);
                b0[nf][1] = __float_as_uint(Bs0[(kk + 4) * BPAD + n]);
                b1[nf][0] = __float_as_uint(Bs1[kk * BPAD + n]);
                b1[nf][1] = __float_as_uint(Bs1[(kk + 4) * BPAD + n]);
            }
            #pragma unroll
            for (int mf = 0; mf < 2; mf++)
                #pragma unroll
                for (int nf = 0; nf < 4; nf++) {
                    mma_tf32(accz[mf][nf], af[mf], b0[nf]);
                    mma_tf32(acch[mf][nf], af[mf], b1[nf]);
                }
        }
        s  = (s  + 1 == NSTAGE) ? 0 : s  + 1;
        sn = (sn + 1 == NSTAGE) ? 0 : sn + 1;
    }

    // epilogue: a = 1 - sigmoid(yz), b = sigmoid(yz) * yh
    #pragma unroll
    for (int nf = 0; nf < 4; nf++) {
        int col = bn * BN + wn * 32 + nf * 8 + 2 * t;
        float bz0 = bz[col], bz1 = bz[col + 1];
        float bh0 = bh[col], bh1 = bh[col + 1];
        #pragma unroll
        for (int mf = 0; mf < 2; mf++) {
            int row0 = bm * BM + wm * 32 + mf * 16 + g;
            float z0 = 1.f / (1.f + __expf(-(accz[mf][nf][0] + bz0)));
            float z1 = 1.f / (1.f + __expf(-(accz[mf][nf][1] + bz1)));
            float z2 = 1.f / (1.f + __expf(-(accz[mf][nf][2] + bz0)));
            float z3 = 1.f / (1.f + __expf(-(accz[mf][nf][3] + bz1)));
            float2 a01 = make_float2(1.f - z0, 1.f - z1);
            float2 a23 = make_float2(1.f - z2, 1.f - z3);
            float2 b01 = make_float2(z0 * (acch[mf][nf][0] + bh0),
                                     z1 * (acch[mf][nf][1] + bh1));
            float2 b23 = make_float2(z2 * (acch[mf][nf][2] + bh0),
                                     z3 * (acch[mf][nf][3] + bh1));
            *(float2*)&g_a[(size_t)row0 * DD + col] = a01;
            *(float2*)&g_b[(size_t)row0 * DD + col] = b01;
            *(float2*)&g_a[(size_t)(row0 + 8) * DD + col] = a23;
            *(float2*)&g_b[(size_t)(row0 + 8) * DD + col] = b23;
        }
    }
}

// ============================================================
// Scan phase 1: per-chunk composition (float4, 4 channels/thread).
// ============================================================
__global__ void scan_reduce_kernel()
{
    const int tid = threadIdx.x;
    const int c = blockIdx.x, b = blockIdx.y;
    const float4* A4 = (const float4*)g_a;
    const float4* B4 = (const float4*)g_b;
    size_t base = ((size_t)(b * TT + c * CHUNK)) * (DD / 4) + tid;
    float4 A = make_float4(1.f, 1.f, 1.f, 1.f);
    float4 Bc = make_float4(0.f, 0.f, 0.f, 0.f);
    #pragma unroll 8
    for (int i = 0; i < CHUNK; i++) {
        float4 a = A4[base], v = B4[base];
        Bc.x = fmaf(a.x, Bc.x, v.x); A.x *= a.x;
        Bc.y = fmaf(a.y, Bc.y, v.y); A.y *= a.y;
        Bc.z = fmaf(a.z, Bc.z, v.z); A.z *= a.z;
        Bc.w = fmaf(a.w, Bc.w, v.w); A.w *= a.w;
        base += DD / 4;
    }
    int idx = (b * NCH + c) * (DD / 4) + tid;
    ((float4*)g_cA)[idx] = A;
    ((float4*)g_cB)[idx] = Bc;
}

// ============================================================
// Scan phase 2: serial scan over chunk carries.
// ============================================================
__global__ void scan_carry_kernel()
{
    const int tid = threadIdx.x;
    const int b = blockIdx.x;
    float4 h = make_float4(0.f, 0.f, 0.f, 0.f);
    #pragma unroll
    for (int c = 0; c < NCH; c++) {
        int idx = (b * NCH + c) * (DD / 4) + tid;
        ((float4*)g_cH)[idx] = h;
        float4 A = ((const float4*)g_cA)[idx];
        float4 Bc = ((const float4*)g_cB)[idx];
        h.x = fmaf(A.x, h.x, Bc.x);
        h.y = fmaf(A.y, h.y, Bc.y);
        h.z = fmaf(A.z, h.z, Bc.z);
        h.w = fmaf(A.w, h.w, Bc.w);
    }
}

// ============================================================
// Scan phase 3: rescan each chunk from carry, write output.
// ============================================================
__global__ void scan_apply_kernel(float4* __restrict__ out)
{
    const int tid = threadIdx.x;
    const int c = blockIdx.x, b = blockIdx.y;
    const float4* A4 = (const float4*)g_a;
    const float4* B4 = (const float4*)g_b;
    size_t base = ((size_t)(b * TT + c * CHUNK)) * (DD / 4) + tid;
    float4 h = ((const float4*)g_cH)[(b * NCH + c) * (DD / 4) + tid];
    #pragma unroll 8
    for (int i = 0; i < CHUNK; i++) {
        float4 a = A4[base], v = B4[base];
        h.x = fmaf(a.x, h.x, v.x);
        h.y = fmaf(a.y, h.y, v.y);
        h.z = fmaf(a.z, h.z, v.z);
        h.w = fmaf(a.w, h.w, v.w);
        out[base] = h;
        base += DD / 4;
    }
}

// ============================================================
extern "C" void kernel_launch(void* const* d_in, const int* in_sizes, int n_in,
                              void* d_out, int out_size)
{
    const float* x  = (const float*)d_in[0];
    const float* Wz = (const float*)d_in[1];
    const float* bz = (const float*)d_in[2];
    const float* Wh = (const float*)d_in[3];
    const float* bh = (const float*)d_in[4];
    float4* out = (float4*)d_out;

    const int smem_bytes = NSTAGE * STG_WORDS * 4;   // 77,824 B
    cudaFuncSetAttribute(dual_gemm_kernel,
                         cudaFuncAttributeMaxDynamicSharedMemorySize, smem_bytes);

    // tf32 pre-rounding
    float* xr;  cudaGetSymbolAddress((void**)&xr,  g_xr);
    float* wzr; cudaGetSymbolAddress((void**)&wzr, g_wzr);
    float* whr; cudaGetSymbolAddress((void**)&whr, g_whr);
    int n4x = MM * DD / 4;
    int n4w = DD * DD / 4;
    round_tf32_kernel<<<(n4x + 255) / 256, 256>>>((const float4*)x,  (float4*)xr,  n4x);
    round_tf32_kernel<<<(n4w + 255) / 256, 256>>>((const float4*)Wz, (float4*)wzr, n4w);
    round_tf32_kernel<<<(n4w + 255) / 256, 256>>>((const float4*)Wh, (float4*)whr, n4w);

    // fused dual GEMM -> (a, b)
    dual_gemm_kernel<<<dim3(DD / BN, MM / BM), 256, smem_bytes>>>(bz, bh);

    // chunked associative scan
    scan_reduce_kernel<<<dim3(NCH, BQ), 256>>>();
    scan_carry_kernel<<<BQ, 256>>>();
    scan_apply_kernel<<<dim3(NCH, BQ), 256>>>(out);
}

// round 10
// speedup vs baseline: 1.9524x; 1.7270x over previous
#include <cuda_runtime.h>
#include <cuda_fp16.h>
#include <cstdint>

#define BQ 4
#define TT 4096
#define DD 1024
#define MM (BQ * TT)          // 16384 rows
#define NCH 64                // chunks along T
#define CHUNK 64              // T / NCH

#define BM 128
#define BN 64
#define BK 32
#define NSTG 4
#define NKT (DD / BK)         // 32
#define KPAD 40               // halfs per row (80 B, 16B-aligned, ldmatrix conflict-free)
#define A_HALFS (BM * KPAD)               // 5120
#define B_HALFS (BN * KPAD)               // 2560
#define STG_HALFS (A_HALFS + 2 * B_HALFS) // 10240 halfs = 20480 B
#define STG_BYTES (STG_HALFS * 2)
#define SMEM_BYTES (NSTG * STG_BYTES)     // 81920

// ---- scratch (__device__ globals: allocation-free rule) ----
__device__ __half g_xh[(size_t)MM * DD];    // fp16 X            [m][k]
__device__ __half g_wzt[(size_t)DD * DD];   // fp16 Wz^T         [n][k]
__device__ __half g_wht[(size_t)DD * DD];   // fp16 Wh^T         [n][k]
__device__ float g_a[(size_t)MM * DD];      // a_t = 1 - z_t
__device__ float g_b[(size_t)MM * DD];      // b_t = z_t * htilde_t
__device__ float g_cA[BQ * NCH * DD];
__device__ float g_cB[BQ * NCH * DD];
__device__ float g_cH[BQ * NCH * DD];

__device__ __forceinline__ void ldm_x4(uint32_t r[4], uint32_t addr) {
    asm volatile("ldmatrix.sync.aligned.m8n8.x4.shared.b16 {%0,%1,%2,%3}, [%4];"
                 : "=r"(r[0]), "=r"(r[1]), "=r"(r[2]), "=r"(r[3]) : "r"(addr));
}

__device__ __forceinline__ void mma_fp16(float c[4], const uint32_t a[4], const uint32_t b[2]) {
    asm volatile(
        "mma.sync.aligned.m16n8k16.row.col.f32.f16.f16.f32 "
        "{%0,%1,%2,%3}, {%4,%5,%6,%7}, {%8,%9}, {%0,%1,%2,%3};\n"
        : "+f"(c[0]), "+f"(c[1]), "+f"(c[2]), "+f"(c[3])
        : "r"(a[0]), "r"(a[1]), "r"(a[2]), "r"(a[3]),
          "r"(b[0]), "r"(b[1]));
}

// ============================================================
// X -> fp16 (layout preserved).
// ============================================================
__global__ void x_to_half_kernel(const float4* __restrict__ src,
                                 uint2* __restrict__ dst, int n4)
{
    int i = blockIdx.x * blockDim.x + threadIdx.x;
    if (i < n4) {
        float4 v = src[i];
        union { __half2 h2[2]; uint2 u; } o;
        o.h2[0] = __floats2half2_rn(v.x, v.y);
        o.h2[1] = __floats2half2_rn(v.z, v.w);
        dst[i] = o.u;
    }
}

// ============================================================
// W [k][n] f32 -> W^T [n][k] fp16.
// ============================================================
__global__ void transpose_half_kernel(const float* __restrict__ src,
                                      __half* __restrict__ dst)
{
    __shared__ float t[32][33];
    int tx = threadIdx.x, ty = threadIdx.y;
    int k0 = blockIdx.y * 32;
    int n0 = blockIdx.x * 32;
    #pragma unroll
    for (int j = 0; j < 32; j += 8)
        t[ty + j][tx] = src[(size_t)(k0 + ty + j) * DD + n0 + tx];
    __syncthreads();
    #pragma unroll
    for (int j = 0; j < 32; j += 8)
        dst[(size_t)(n0 + ty + j) * DD + k0 + tx] = __float2half(t[tx][ty + j]);
}

// ============================================================
// Fused dual GEMM, fp16 m16n8k16 + ldmatrix. Block 128x64, 8 warps
// = 4(m) x 2(n), warp tile 32x32 per output. 4-stage cp.async, BK=32.
// Epilogue stores a = 1-sigmoid(yz), b = sigmoid(yz)*yh.
// ============================================================
__global__ __launch_bounds__(256, 2)
void dual_gemm_fp16(const float* __restrict__ bz, const float* __restrict__ bh)
{
    extern __shared__ __half smem[];
    const uint32_t sbase = (uint32_t)__cvta_generic_to_shared(smem);

    const int tid  = threadIdx.x;
    const int warp = tid >> 5, lane = tid & 31;
    const int wm = warp >> 1, wn = warp & 1;    // 4 x 2 warp grid
    const int g = lane >> 2, t = lane & 3;
    const int bm = blockIdx.y, bn = blockIdx.x;

    float accz[2][4][4], acch[2][4][4];
    #pragma unroll
    for (int i = 0; i < 2; i++)
        #pragma unroll
        for (int j = 0; j < 4; j++)
            #pragma unroll
            for (int k = 0; k < 4; k++) { accz[i][j][k] = 0.f; acch[i][j][k] = 0.f; }

    // loader coords: 1024 x 16B chunks per stage, 4 per thread
    const int l_row = tid >> 2, l_c8 = tid & 3;

    auto load_stage = [&](int kt, int s) {
        const uint32_t stg = sbase + s * STG_BYTES;
        const size_t kofs = (size_t)kt * BK + l_c8 * 8;
        // A rows 0..63 and 64..127
        {
            const __half* sp = &g_xh[(size_t)(bm * BM + l_row) * DD + kofs];
            uint32_t d = stg + (l_row * KPAD + l_c8 * 8) * 2;
            asm volatile("cp.async.cg.shared.global [%0], [%1], 16;\n" :: "r"(d), "l"(sp));
            const __half* sp2 = sp + (size_t)64 * DD;
            uint32_t d2 = d + 64 * KPAD * 2;
            asm volatile("cp.async.cg.shared.global [%0], [%1], 16;\n" :: "r"(d2), "l"(sp2));
        }
        // Bz rows 0..63, Bh rows 0..63
        {
            const __half* spz = &g_wzt[(size_t)(bn * BN + l_row) * DD + kofs];
            uint32_t dz = stg + (A_HALFS + l_row * KPAD + l_c8 * 8) * 2;
            asm volatile("cp.async.cg.shared.global [%0], [%1], 16;\n" :: "r"(dz), "l"(spz));
            const __half* sph = &g_wht[(size_t)(bn * BN + l_row) * DD + kofs];
            uint32_t dh = dz + B_HALFS * 2;
            asm volatile("cp.async.cg.shared.global [%0], [%1], 16;\n" :: "r"(dh), "l"(sph));
        }
    };

    // prologue: stages 0..NSTG-2
    #pragma unroll
    for (int kt = 0; kt < NSTG - 1; kt++) {
        load_stage(kt, kt);
        asm volatile("cp.async.commit_group;\n");
    }

    // ldmatrix lane addressing: mat j = lane>>3 -> row += (j&1)*8, col += (j>>1)*8
    const int lm_r = lane & 7;
    const int lm_rowoff = ((lane >> 3) & 1) * 8 + lm_r;
    const int lm_coloff = (lane >> 4) * 8;

    for (int kt = 0; kt < NKT; kt++) {
        const int s = kt & (NSTG - 1);
        asm volatile("cp.async.wait_group %0;\n" :: "n"(NSTG - 2));
        __syncthreads();

        int ktn = kt + NSTG - 1;
        if (ktn < NKT) load_stage(ktn, ktn & (NSTG - 1));
        asm volatile("cp.async.commit_group;\n");

        const uint32_t Aw  = sbase + s * STG_BYTES + (wm * 32) * KPAD * 2;
        const uint32_t Bw0 = sbase + s * STG_BYTES + (A_HALFS + wn * 32 * KPAD) * 2;
        const uint32_t Bw1 = Bw0 + B_HALFS * 2;

        #pragma unroll
        for (int ks = 0; ks < 2; ks++) {
            const int k0 = ks * 16;
            const uint32_t cbytes = (k0 + lm_coloff) * 2;

            uint32_t af[2][4];
            #pragma unroll
            for (int mf = 0; mf < 2; mf++)
                ldm_x4(af[mf], Aw + (mf * 16 + lm_rowoff) * KPAD * 2 + cbytes);

            uint32_t bfz[4][2], bfh[4][2];
            #pragma unroll
            for (int nf2 = 0; nf2 < 2; nf2++) {
                uint32_t rowb = (nf2 * 16 + lm_rowoff) * KPAD * 2 + cbytes;
                uint32_t q[4];
                ldm_x4(q, Bw0 + rowb);
                bfz[2 * nf2][0] = q[0]; bfz[2 * nf2 + 1][0] = q[1];
                bfz[2 * nf2][1] = q[2]; bfz[2 * nf2 + 1][1] = q[3];
                ldm_x4(q, Bw1 + rowb);
                bfh[2 * nf2][0] = q[0]; bfh[2 * nf2 + 1][0] = q[1];
                bfh[2 * nf2][1] = q[2]; bfh[2 * nf2 + 1][1] = q[3];
            }

            #pragma unroll
            for (int mf = 0; mf < 2; mf++)
                #pragma unroll
                for (int nf = 0; nf < 4; nf++) {
                    mma_fp16(accz[mf][nf], af[mf], bfz[nf]);
                    mma_fp16(acch[mf][nf], af[mf], bfh[nf]);
                }
        }
    }

    // epilogue: a = 1 - sigmoid(yz), b = sigmoid(yz) * yh
    #pragma unroll
    for (int nf = 0; nf < 4; nf++) {
        int col = bn * BN + wn * 32 + nf * 8 + 2 * t;
        float bz0 = bz[col], bz1 = bz[col + 1];
        float bh0 = bh[col], bh1 = bh[col + 1];
        #pragma unroll
        for (int mf = 0; mf < 2; mf++) {
            int row0 = bm * BM + wm * 32 + mf * 16 + g;
            float z0 = 1.f / (1.f + __expf(-(accz[mf][nf][0] + bz0)));
            float z1 = 1.f / (1.f + __expf(-(accz[mf][nf][1] + bz1)));
            float z2 = 1.f / (1.f + __expf(-(accz[mf][nf][2] + bz0)));
            float z3 = 1.f / (1.f + __expf(-(accz[mf][nf][3] + bz1)));
            float2 a01 = make_float2(1.f - z0, 1.f - z1);
            float2 a23 = make_float2(1.f - z2, 1.f - z3);
            float2 b01 = make_float2(z0 * (acch[mf][nf][0] + bh0),
                                     z1 * (acch[mf][nf][1] + bh1));
            float2 b23 = make_float2(z2 * (acch[mf][nf][2] + bh0),
                                     z3 * (acch[mf][nf][3] + bh1));
            *(float2*)&g_a[(size_t)row0 * DD + col] = a01;
            *(float2*)&g_b[(size_t)row0 * DD + col] = b01;
            *(float2*)&g_a[(size_t)(row0 + 8) * DD + col] = a23;
            *(float2*)&g_b[(size_t)(row0 + 8) * DD + col] = b23;
        }
    }
}

// ============================================================
// Scan phase 1: per-chunk composition (float4, 4 channels/thread).
// ============================================================
__global__ void scan_reduce_kernel()
{
    const int tid = threadIdx.x;
    const int c = blockIdx.x, b = blockIdx.y;
    const float4* A4 = (const float4*)g_a;
    const float4* B4 = (const float4*)g_b;
    size_t base = ((size_t)(b * TT + c * CHUNK)) * (DD / 4) + tid;
    float4 A = make_float4(1.f, 1.f, 1.f, 1.f);
    float4 Bc = make_float4(0.f, 0.f, 0.f, 0.f);
    #pragma unroll 8
    for (int i = 0; i < CHUNK; i++) {
        float4 a = A4[base], v = B4[base];
        Bc.x = fmaf(a.x, Bc.x, v.x); A.x *= a.x;
        Bc.y = fmaf(a.y, Bc.y, v.y); A.y *= a.y;
        Bc.z = fmaf(a.z, Bc.z, v.z); A.z *= a.z;
        Bc.w = fmaf(a.w, Bc.w, v.w); A.w *= a.w;
        base += DD / 4;
    }
    int idx = (b * NCH + c) * (DD / 4) + tid;
    ((float4*)g_cA)[idx] = A;
    ((float4*)g_cB)[idx] = Bc;
}

// ============================================================
// Scan phase 2: serial scan over chunk carries.
// ============================================================
__global__ void scan_carry_kernel()
{
    const int tid = threadIdx.x;
    const int b = blockIdx.x;
    float4 h = make_float4(0.f, 0.f, 0.f, 0.f);
    #pragma unroll
    for (int c = 0; c < NCH; c++) {
        int idx = (b * NCH + c) * (DD / 4) + tid;
        ((float4*)g_cH)[idx] = h;
        float4 A = ((const float4*)g_cA)[idx];
        float4 Bc = ((const float4*)g_cB)[idx];
        h.x = fmaf(A.x, h.x, Bc.x);
        h.y = fmaf(A.y, h.y, Bc.y);
        h.z = fmaf(A.z, h.z, Bc.z);
        h.w = fmaf(A.w, h.w, Bc.w);
    }
}

// ============================================================
// Scan phase 3: rescan each chunk from carry, write output.
// ============================================================
__global__ void scan_apply_kernel(float4* __restrict__ out)
{
    const int tid = threadIdx.x;
    const int c = blockIdx.x, b = blockIdx.y;
    const float4* A4 = (const float4*)g_a;
    const float4* B4 = (const float4*)g_b;
    size_t base = ((size_t)(b * TT + c * CHUNK)) * (DD / 4) + tid;
    float4 h = ((const float4*)g_cH)[(b * NCH + c) * (DD / 4) + tid];
    #pragma unroll 8
    for (int i = 0; i < CHUNK; i++) {
        float4 a = A4[base], v = B4[base];
        h.x = fmaf(a.x, h.x, v.x);
        h.y = fmaf(a.y, h.y, v.y);
        h.z = fmaf(a.z, h.z, v.z);
        h.w = fmaf(a.w, h.w, v.w);
        out[base] = h;
        base += DD / 4;
    }
}

// ============================================================
extern "C" void kernel_launch(void* const* d_in, const int* in_sizes, int n_in,
                              void* d_out, int out_size)
{
    const float* x  = (const float*)d_in[0];
    const float* Wz = (const float*)d_in[1];
    const float* bz = (const float*)d_in[2];
    const float* Wh = (const float*)d_in[3];
    const float* bh = (const float*)d_in[4];
    float4* out = (float4*)d_out;

    cudaFuncSetAttribute(dual_gemm_fp16,
                         cudaFuncAttributeMaxDynamicSharedMemorySize, SMEM_BYTES);

    __half* xh;  cudaGetSymbolAddress((void**)&xh,  g_xh);
    __half* wzt; cudaGetSymbolAddress((void**)&wzt, g_wzt);
    __half* wht; cudaGetSymbolAddress((void**)&wht, g_wht);

    // fp16 conversion (X) and transpose+convert (weights -> [N,K])
    int n4x = MM * DD / 4;
    x_to_half_kernel<<<(n4x + 255) / 256, 256>>>((const float4*)x, (uint2*)xh, n4x);
    transpose_half_kernel<<<dim3(32, 32), dim3(32, 8)>>>(Wz, wzt);
    transpose_half_kernel<<<dim3(32, 32), dim3(32, 8)>>>(Wh, wht);

    // fused dual GEMM (fp16 tensor cores) -> (a, b)
    dual_gemm_fp16<<<dim3(DD / BN, MM / BM), 256, SMEM_BYTES>>>(bz, bh);

    // chunked associative scan
    scan_reduce_kernel<<<dim3(NCH, BQ), 256>>>();
    scan_carry_kernel<<<BQ, 256>>>();
    scan_apply_kernel<<<dim3(NCH, BQ), 256>>>(out);
}

// round 11
// speedup vs baseline: 2.1321x; 1.0920x over previous
#include <cuda_runtime.h>
#include <cuda_fp16.h>
#include <cstdint>

#define BQ 4
#define TT 4096
#define DD 1024
#define MM (BQ * TT)          // 16384 rows
#define NCH 64                // chunks along T
#define CHUNK 64              // T / NCH

#define BM 128
#define BN 64
#define BK 64
#define NSTG 3
#define NKT (DD / BK)         // 16
#define KPAD 72               // halfs per row (144 B; ldmatrix conflict-free: 9r mod 8 distinct)
#define A_HALFS (BM * KPAD)               // 9216
#define B_HALFS (BN * KPAD)               // 4608
#define STG_HALFS (A_HALFS + 2 * B_HALFS) // 18432 halfs
#define STG_BYTES (STG_HALFS * 2)         // 36864
#define SMEM_BYTES (NSTG * STG_BYTES)     // 110592
#define A_BYTES (A_HALFS * 2)             // 18432
#define B_BYTES (B_HALFS * 2)             // 9216

// ---- scratch (__device__ globals: allocation-free rule) ----
__device__ __half g_xh[(size_t)MM * DD];    // fp16 X            [m][k]
__device__ __half g_wzt[(size_t)DD * DD];   // fp16 Wz^T         [n][k]
__device__ __half g_wht[(size_t)DD * DD];   // fp16 Wh^T         [n][k]
__device__ float g_a[(size_t)MM * DD];      // a_t = 1 - z_t
__device__ float g_b[(size_t)MM * DD];      // b_t = z_t * htilde_t
__device__ float g_cA[BQ * NCH * DD];
__device__ float g_cB[BQ * NCH * DD];
__device__ float g_cH[BQ * NCH * DD];

__device__ __forceinline__ void ldm_x4(uint32_t r[4], uint32_t addr) {
    asm volatile("ldmatrix.sync.aligned.m8n8.x4.shared.b16 {%0,%1,%2,%3}, [%4];"
                 : "=r"(r[0]), "=r"(r[1]), "=r"(r[2]), "=r"(r[3]) : "r"(addr));
}

__device__ __forceinline__ void mma_fp16(float c[4], const uint32_t a[4], const uint32_t b[2]) {
    asm volatile(
        "mma.sync.aligned.m16n8k16.row.col.f32.f16.f16.f32 "
        "{%0,%1,%2,%3}, {%4,%5,%6,%7}, {%8,%9}, {%0,%1,%2,%3};\n"
        : "+f"(c[0]), "+f"(c[1]), "+f"(c[2]), "+f"(c[3])
        : "r"(a[0]), "r"(a[1]), "r"(a[2]), "r"(a[3]),
          "r"(b[0]), "r"(b[1]));
}

// ============================================================
// X -> fp16 (layout preserved).
// ============================================================
__global__ void x_to_half_kernel(const float4* __restrict__ src,
                                 uint2* __restrict__ dst, int n4)
{
    int i = blockIdx.x * blockDim.x + threadIdx.x;
    if (i < n4) {
        float4 v = src[i];
        union { __half2 h2[2]; uint2 u; } o;
        o.h2[0] = __floats2half2_rn(v.x, v.y);
        o.h2[1] = __floats2half2_rn(v.z, v.w);
        dst[i] = o.u;
    }
}

// ============================================================
// W [k][n] f32 -> W^T [n][k] fp16.
// ============================================================
__global__ void transpose_half_kernel(const float* __restrict__ src,
                                      __half* __restrict__ dst)
{
    __shared__ float t[32][33];
    int tx = threadIdx.x, ty = threadIdx.y;
    int k0 = blockIdx.y * 32;
    int n0 = blockIdx.x * 32;
    #pragma unroll
    for (int j = 0; j < 32; j += 8)
        t[ty + j][tx] = src[(size_t)(k0 + ty + j) * DD + n0 + tx];
    __syncthreads();
    #pragma unroll
    for (int j = 0; j < 32; j += 8)
        dst[(size_t)(n0 + ty + j) * DD + k0 + tx] = __float2half(t[tx][ty + j]);
}

// ============================================================
// Fused dual GEMM, fp16 m16n8k16 + ldmatrix. Block 128x64, 8 warps
// = 4(m) x 2(n), warp tile 32x32 per output. BK=64, 3-stage cp.async.
// All ldmatrix offsets loop-invariant; only the stage base rotates.
// Epilogue stores a = 1-sigmoid(yz), b = sigmoid(yz)*yh.
// ============================================================
__global__ __launch_bounds__(256, 2)
void dual_gemm_fp16(const float* __restrict__ bz, const float* __restrict__ bh)
{
    extern __shared__ __half smem[];
    const uint32_t sb0 = (uint32_t)__cvta_generic_to_shared(smem);
    const uint32_t sb2 = sb0 + 2 * STG_BYTES;

    const int tid  = threadIdx.x;
    const int warp = tid >> 5, lane = tid & 31;
    const int wm = warp >> 1, wn = warp & 1;    // 4 x 2 warp grid
    const int g = lane >> 2, t = lane & 3;
    const int bm = blockIdx.y, bn = blockIdx.x;

    float accz[2][4][4], acch[2][4][4];
    #pragma unroll
    for (int i = 0; i < 2; i++)
        #pragma unroll
        for (int j = 0; j < 4; j++)
            #pragma unroll
            for (int k = 0; k < 4; k++) { accz[i][j][k] = 0.f; acch[i][j][k] = 0.f; }

    // ---- loop-invariant loader coords ----
    // A: 1024 x 16B chunks (4/thread); B: 512 chunks each (2/thread each)
    const int a_row0 = tid >> 3, a_c8 = tid & 7;       // +32 rows per i
    const int b_row0 = tid >> 3;                        // +32 rows per i

    auto load_stage = [&](int kt, uint32_t stg) {
        const size_t kofs = (size_t)kt * BK + a_c8 * 8;
        #pragma unroll
        for (int i = 0; i < 4; i++) {
            int row = a_row0 + i * 32;
            const __half* sp = &g_xh[(size_t)(bm * BM + row) * DD + kofs];
            uint32_t d = stg + (row * KPAD + a_c8 * 8) * 2;
            asm volatile("cp.async.cg.shared.global [%0], [%1], 16;\n" :: "r"(d), "l"(sp));
        }
        #pragma unroll
        for (int i = 0; i < 2; i++) {
            int row = b_row0 + i * 32;
            const __half* spz = &g_wzt[(size_t)(bn * BN + row) * DD + kofs];
            uint32_t dz = stg + A_BYTES + (row * KPAD + a_c8 * 8) * 2;
            asm volatile("cp.async.cg.shared.global [%0], [%1], 16;\n" :: "r"(dz), "l"(spz));
            const __half* sph = &g_wht[(size_t)(bn * BN + row) * DD + kofs];
            uint32_t dh = dz + B_BYTES;
            asm volatile("cp.async.cg.shared.global [%0], [%1], 16;\n" :: "r"(dh), "l"(sph));
        }
    };

    // ---- loop-invariant ldmatrix relative offsets ----
    const int lm_rowoff = ((lane >> 3) & 1) * 8 + (lane & 7);
    const int lm_coloff = (lane >> 4) * 8;
    uint32_t a_rel[2], b_rel[2];
    #pragma unroll
    for (int mf = 0; mf < 2; mf++)
        a_rel[mf] = (uint32_t)((wm * 32 + mf * 16 + lm_rowoff) * KPAD + lm_coloff) * 2;
    #pragma unroll
    for (int nf2 = 0; nf2 < 2; nf2++)
        b_rel[nf2] = A_BYTES +
            (uint32_t)((wn * 32 + nf2 * 16 + lm_rowoff) * KPAD + lm_coloff) * 2;

    // prologue: stages 0, 1
    load_stage(0, sb0);
    asm volatile("cp.async.commit_group;\n");
    load_stage(1, sb0 + STG_BYTES);
    asm volatile("cp.async.commit_group;\n");

    uint32_t cs = sb0;   // compute stage base (stage kt%3)
    uint32_t ls = sb2;   // load stage base for kt+2 ((kt+2)%3)

    for (int kt = 0; kt < NKT; kt++) {
        asm volatile("cp.async.wait_group 1;\n");
        __syncthreads();

        if (kt + 2 < NKT) load_stage(kt + 2, ls);
        asm volatile("cp.async.commit_group;\n");

        #pragma unroll
        for (int ks = 0; ks < 4; ks++) {
            const uint32_t kb = cs + ks * 32;   // ks*16 halfs = 32 B

            uint32_t af[2][4];
            #pragma unroll
            for (int mf = 0; mf < 2; mf++)
                ldm_x4(af[mf], kb + a_rel[mf]);

            uint32_t bfz[4][2], bfh[4][2];
            #pragma unroll
            for (int nf2 = 0; nf2 < 2; nf2++) {
                uint32_t q[4];
                ldm_x4(q, kb + b_rel[nf2]);
                bfz[2 * nf2][0] = q[0]; bfz[2 * nf2 + 1][0] = q[1];
                bfz[2 * nf2][1] = q[2]; bfz[2 * nf2 + 1][1] = q[3];
                ldm_x4(q, kb + b_rel[nf2] + B_BYTES);
                bfh[2 * nf2][0] = q[0]; bfh[2 * nf2 + 1][0] = q[1];
                bfh[2 * nf2][1] = q[2]; bfh[2 * nf2 + 1][1] = q[3];
            }

            #pragma unroll
            for (int mf = 0; mf < 2; mf++)
                #pragma unroll
                for (int nf = 0; nf < 4; nf++) {
                    mma_fp16(accz[mf][nf], af[mf], bfz[nf]);
                    mma_fp16(acch[mf][nf], af[mf], bfh[nf]);
                }
        }

        cs = (cs == sb2) ? sb0 : cs + STG_BYTES;
        ls = (ls == sb2) ? sb0 : ls + STG_BYTES;
    }

    // epilogue: a = 1 - sigmoid(yz), b = sigmoid(yz) * yh
    #pragma unroll
    for (int nf = 0; nf < 4; nf++) {
        int col = bn * BN + wn * 32 + nf * 8 + 2 * t;
        float bz0 = bz[col], bz1 = bz[col + 1];
        float bh0 = bh[col], bh1 = bh[col + 1];
        #pragma unroll
        for (int mf = 0; mf < 2; mf++) {
            int row0 = bm * BM + wm * 32 + mf * 16 + g;
            float z0 = 1.f / (1.f + __expf(-(accz[mf][nf][0] + bz0)));
            float z1 = 1.f / (1.f + __expf(-(accz[mf][nf][1] + bz1)));
            float z2 = 1.f / (1.f + __expf(-(accz[mf][nf][2] + bz0)));
            float z3 = 1.f / (1.f + __expf(-(accz[mf][nf][3] + bz1)));
            float2 a01 = make_float2(1.f - z0, 1.f - z1);
            float2 a23 = make_float2(1.f - z2, 1.f - z3);
            float2 b01 = make_float2(z0 * (acch[mf][nf][0] + bh0),
                                     z1 * (acch[mf][nf][1] + bh1));
            float2 b23 = make_float2(z2 * (acch[mf][nf][2] + bh0),
                                     z3 * (acch[mf][nf][3] + bh1));
            *(float2*)&g_a[(size_t)row0 * DD + col] = a01;
            *(float2*)&g_b[(size_t)row0 * DD + col] = b01;
            *(float2*)&g_a[(size_t)(row0 + 8) * DD + col] = a23;
            *(float2*)&g_b[(size_t)(row0 + 8) * DD + col] = b23;
        }
    }
}

// ============================================================
// Scan phase 1: per-chunk composition (float4, 4 channels/thread).
// ============================================================
__global__ void scan_reduce_kernel()
{
    const int tid = threadIdx.x;
    const int c = blockIdx.x, b = blockIdx.y;
    const float4* A4 = (const float4*)g_a;
    const float4* B4 = (const float4*)g_b;
    size_t base = ((size_t)(b * TT + c * CHUNK)) * (DD / 4) + tid;
    float4 A = make_float4(1.f, 1.f, 1.f, 1.f);
    float4 Bc = make_float4(0.f, 0.f, 0.f, 0.f);
    #pragma unroll 8
    for (int i = 0; i < CHUNK; i++) {
        float4 a = A4[base], v = B4[base];
        Bc.x = fmaf(a.x, Bc.x, v.x); A.x *= a.x;
        Bc.y = fmaf(a.y, Bc.y, v.y); A.y *= a.y;
        Bc.z = fmaf(a.z, Bc.z, v.z); A.z *= a.z;
        Bc.w = fmaf(a.w, Bc.w, v.w); A.w *= a.w;
        base += DD / 4;
    }
    int idx = (b * NCH + c) * (DD / 4) + tid;
    ((float4*)g_cA)[idx] = A;
    ((float4*)g_cB)[idx] = Bc;
}

// ============================================================
// Scan phase 2: serial scan over chunk carries.
// ============================================================
__global__ void scan_carry_kernel()
{
    const int tid = threadIdx.x;
    const int b = blockIdx.x;
    float4 h = make_float4(0.f, 0.f, 0.f, 0.f);
    #pragma unroll
    for (int c = 0; c < NCH; c++) {
        int idx = (b * NCH + c) * (DD / 4) + tid;
        ((float4*)g_cH)[idx] = h;
        float4 A = ((const float4*)g_cA)[idx];
        float4 Bc = ((const float4*)g_cB)[idx];
        h.x = fmaf(A.x, h.x, Bc.x);
        h.y = fmaf(A.y, h.y, Bc.y);
        h.z = fmaf(A.z, h.z, Bc.z);
        h.w = fmaf(A.w, h.w, Bc.w);
    }
}

// ============================================================
// Scan phase 3: rescan each chunk from carry, write output.
// ============================================================
__global__ void scan_apply_kernel(float4* __restrict__ out)
{
    const int tid = threadIdx.x;
    const int c = blockIdx.x, b = blockIdx.y;
    const float4* A4 = (const float4*)g_a;
    const float4* B4 = (const float4*)g_b;
    size_t base = ((size_t)(b * TT + c * CHUNK)) * (DD / 4) + tid;
    float4 h = ((const float4*)g_cH)[(b * NCH + c) * (DD / 4) + tid];
    #pragma unroll 8
    for (int i = 0; i < CHUNK; i++) {
        float4 a = A4[base], v = B4[base];
        h.x = fmaf(a.x, h.x, v.x);
        h.y = fmaf(a.y, h.y, v.y);
        h.z = fmaf(a.z, h.z, v.z);
        h.w = fmaf(a.w, h.w, v.w);
        out[base] = h;
        base += DD / 4;
    }
}

// ============================================================
extern "C" void kernel_launch(void* const* d_in, const int* in_sizes, int n_in,
                              void* d_out, int out_size)
{
    const float* x  = (const float*)d_in[0];
    const float* Wz = (const float*)d_in[1];
    const float* bz = (const float*)d_in[2];
    const float* Wh = (const float*)d_in[3];
    const float* bh = (const float*)d_in[4];
    float4* out = (float4*)d_out;

    cudaFuncSetAttribute(dual_gemm_fp16,
                         cudaFuncAttributeMaxDynamicSharedMemorySize, SMEM_BYTES);

    __half* xh;  cudaGetSymbolAddress((void**)&xh,  g_xh);
    __half* wzt; cudaGetSymbolAddress((void**)&wzt, g_wzt);
    __half* wht; cudaGetSymbolAddress((void**)&wht, g_wht);

    // fp16 conversion (X) and transpose+convert (weights -> [N,K])
    int n4x = MM * DD / 4;
    x_to_half_kernel<<<(n4x + 255) / 256, 256>>>((const float4*)x, (uint2*)xh, n4x);
    transpose_half_kernel<<<dim3(32, 32), dim3(32, 8)>>>(Wz, wzt);
    transpose_half_kernel<<<dim3(32, 32), dim3(32, 8)>>>(Wh, wht);

    // fused dual GEMM (fp16 tensor cores) -> (a, b)
    dual_gemm_fp16<<<dim3(DD / BN, MM / BM), 256, SMEM_BYTES>>>(bz, bh);

    // chunked associative scan
    scan_reduce_kernel<<<dim3(NCH, BQ), 256>>>();
    scan_carry_kernel<<<BQ, 256>>>();
    scan_apply_kernel<<<dim3(NCH, BQ), 256>>>(out);
}